// round 1
// baseline (speedup 1.0000x reference)
#include <cuda_runtime.h>
#include <cuda_bf16.h>
#include <cstdint>

// Problem constants
#define N_MET   100000
#define N_RXN   50000
#define E_SUB   2000000
#define E_ALL   4000000
#define MSG_DIM 16
#define HIDDEN  32

// Persistent scratch: per-reaction accumulated messages [N_RXN][16]
__device__ float g_hrxn[N_RXN * MSG_DIM];

// ---------------------------------------------------------------------------
// helpers: packed f32x2 math + fast approx transcendentals
// ---------------------------------------------------------------------------
__device__ __forceinline__ unsigned long long pack2(float a, float b) {
    unsigned long long r;
    asm("mov.b64 %0, {%1,%2};" : "=l"(r) : "f"(a), "f"(b));
    return r;
}
__device__ __forceinline__ unsigned long long fma2(unsigned long long a,
                                                   unsigned long long b,
                                                   unsigned long long c) {
    unsigned long long d;
    asm("fma.rn.f32x2 %0, %1, %2, %3;" : "=l"(d) : "l"(a), "l"(b), "l"(c));
    return d;
}
__device__ __forceinline__ float2 unpack2(unsigned long long a) {
    float2 f;
    asm("mov.b64 {%0,%1}, %2;" : "=f"(f.x), "=f"(f.y) : "l"(a));
    return f;
}
__device__ __forceinline__ float fast_ex2(float x) {
    float y; asm("ex2.approx.ftz.f32 %0, %1;" : "=f"(y) : "f"(x)); return y;
}
__device__ __forceinline__ float fast_rcp(float x) {
    float y; asm("rcp.approx.ftz.f32 %0, %1;" : "=f"(y) : "f"(x)); return y;
}
// tanh(u) = 1 - 2/(exp(2u)+1); input pre-scaled by 2*log2(e), so arg is ex2-ready
__device__ __forceinline__ float tanh_from_scaled(float u_scaled) {
    float e = fast_ex2(u_scaled);
    float r = fast_rcp(e + 1.0f);
    return fmaf(-2.0f, r, 1.0f);
}

__device__ __forceinline__ void red_add_v4(float* p, float a, float b, float c, float d) {
    asm volatile("red.global.add.v4.f32 [%0], {%1,%2,%3,%4};"
                 :: "l"(p), "f"(a), "f"(b), "f"(c), "f"(d) : "memory");
}
__device__ __forceinline__ void red_add_f32(float* p, float a) {
    asm volatile("red.global.add.f32 [%0], %1;" :: "l"(p), "f"(a) : "memory");
}

// ---------------------------------------------------------------------------
// Kernel 0: zero h_rxn scratch and dxdt output region
// ---------------------------------------------------------------------------
__global__ void zero_kernel(float* __restrict__ dxdt) {
    const int total4 = (N_RXN * MSG_DIM) / 4 + N_MET / 4;  // 200000 + 25000
    const int hr4 = (N_RXN * MSG_DIM) / 4;
    float4 z = make_float4(0.f, 0.f, 0.f, 0.f);
    for (int i = blockIdx.x * blockDim.x + threadIdx.x; i < total4;
         i += gridDim.x * blockDim.x) {
        if (i < hr4) reinterpret_cast<float4*>(g_hrxn)[i] = z;
        else         reinterpret_cast<float4*>(dxdt)[i - hr4] = z;
    }
}

// ---------------------------------------------------------------------------
// Kernel 1: per-edge message MLP + scatter-add into g_hrxn
//   msg = tanh([x,s] @ W1m + b1m) @ W2m + b2m      (2->32->16)
// ---------------------------------------------------------------------------
#define K1_TPB 256
#define K1_EPT 4
#define K1_EPB (K1_TPB * K1_EPT)

__global__ __launch_bounds__(K1_TPB)
void edge_msg_kernel(const float* __restrict__ x_met,
                     const float* __restrict__ sto_sub,
                     const float* __restrict__ W1m,
                     const float* __restrict__ b1m,
                     const float* __restrict__ W2m,
                     const float* __restrict__ b2m,
                     const int*   __restrict__ met_sub,
                     const int*   __restrict__ rxn_sub) {
    __shared__ float4 sW1[HIDDEN];            // {a*C, b*C, c*C, 0}
    __shared__ float4 sW2[HIDDEN][4];         // row j of W2m as 4x float4
    __shared__ float  sB2[MSG_DIM];

    const int t = threadIdx.x;
    if (t < HIDDEN) {
        const float C = 2.8853900817779268f;  // 2*log2(e)
        sW1[t] = make_float4(W1m[t] * C, W1m[HIDDEN + t] * C, b1m[t] * C, 0.f);
    }
    if (t < HIDDEN * 4) {
        reinterpret_cast<float4*>(sW2)[t] = reinterpret_cast<const float4*>(W2m)[t];
    }
    if (t < MSG_DIM) sB2[t] = b2m[t];
    __syncthreads();

    const int base = blockIdx.x * K1_EPB + t;
    float x[K1_EPT], s[K1_EPT];
    int   rx[K1_EPT];
    #pragma unroll
    for (int k = 0; k < K1_EPT; k++) {
        int e = base + k * K1_TPB;
        if (e < E_SUB) {
            x[k]  = x_met[met_sub[e]];
            s[k]  = sto_sub[e];
            rx[k] = rxn_sub[e];
        } else {
            x[k] = 0.f; s[k] = 0.f; rx[k] = -1;
        }
    }

    // accumulators: MSG_DIM floats per edge, as 8 packed f32x2 each, init = b2m
    unsigned long long acc[K1_EPT][MSG_DIM / 2];
    {
        unsigned long long binit[MSG_DIM / 2];
        #pragma unroll
        for (int q = 0; q < MSG_DIM / 2; q++) binit[q] = pack2(sB2[2 * q], sB2[2 * q + 1]);
        #pragma unroll
        for (int k = 0; k < K1_EPT; k++)
            #pragma unroll
            for (int q = 0; q < MSG_DIM / 2; q++) acc[k][q] = binit[q];
    }

    #pragma unroll 4
    for (int j = 0; j < HIDDEN; j++) {
        float4 w1 = sW1[j];
        // W2 row j -> 8 packed pairs (broadcast LDS, amortized over K1_EPT edges)
        unsigned long long w2p[MSG_DIM / 2];
        #pragma unroll
        for (int q = 0; q < 4; q++) {
            float4 w = sW2[j][q];
            w2p[2 * q]     = pack2(w.x, w.y);
            w2p[2 * q + 1] = pack2(w.z, w.w);
        }
        #pragma unroll
        for (int k = 0; k < K1_EPT; k++) {
            float u = fmaf(x[k], w1.x, fmaf(s[k], w1.y, w1.z));  // already *2log2e
            float h = tanh_from_scaled(u);
            unsigned long long hh = pack2(h, h);
            #pragma unroll
            for (int q = 0; q < MSG_DIM / 2; q++)
                acc[k][q] = fma2(hh, w2p[q], acc[k][q]);
        }
    }

    #pragma unroll
    for (int k = 0; k < K1_EPT; k++) {
        if (rx[k] >= 0) {
            float* p = g_hrxn + (size_t)rx[k] * MSG_DIM;
            #pragma unroll
            for (int q = 0; q < 4; q++) {
                float2 a = unpack2(acc[k][2 * q]);
                float2 b = unpack2(acc[k][2 * q + 1]);
                red_add_v4(p + 4 * q, a.x, a.y, b.x, b.y);
            }
        }
    }
}

// ---------------------------------------------------------------------------
// Kernel 2: per-reaction rate MLP
//   v = softplus( tanh(h_rxn @ W1r + b1r) @ W2r + b2r )   (16->32->1)
// ---------------------------------------------------------------------------
__global__ __launch_bounds__(256)
void rate_kernel(const float* __restrict__ W1r,
                 const float* __restrict__ b1r,
                 const float* __restrict__ W2r,
                 const float* __restrict__ b2r,
                 float* __restrict__ v_out) {
    __shared__ float sW1r[MSG_DIM * HIDDEN];  // [16][32] row-major
    __shared__ float sb1r[HIDDEN];
    __shared__ float sW2r[HIDDEN];
    __shared__ float sb2r;

    int t = threadIdx.x;
    for (int i = t; i < MSG_DIM * HIDDEN; i += blockDim.x) sW1r[i] = W1r[i];
    if (t < HIDDEN) { sb1r[t] = b1r[t]; sW2r[t] = W2r[t]; }
    if (t == 0) sb2r = b2r[0];
    __syncthreads();

    int r = blockIdx.x * blockDim.x + t;
    if (r >= N_RXN) return;

    float h[MSG_DIM];
    const float4* hp = reinterpret_cast<const float4*>(g_hrxn + (size_t)r * MSG_DIM);
    #pragma unroll
    for (int q = 0; q < 4; q++) {
        float4 hv = hp[q];
        h[4 * q] = hv.x; h[4 * q + 1] = hv.y; h[4 * q + 2] = hv.z; h[4 * q + 3] = hv.w;
    }

    const float C = 2.8853900817779268f;
    float y = sb2r;
    #pragma unroll 8
    for (int j = 0; j < HIDDEN; j++) {
        float a = sb1r[j];
        #pragma unroll
        for (int k = 0; k < MSG_DIM; k++) a = fmaf(h[k], sW1r[k * HIDDEN + j], a);
        float z = tanh_from_scaled(a * C);
        y = fmaf(z, sW2r[j], y);
    }
    // numerically stable softplus
    float sp = fmaxf(y, 0.f) + log1pf(expf(-fabsf(y)));
    v_out[r] = sp;
}

// ---------------------------------------------------------------------------
// Kernel 3: dxdt scatter:  dxdt[met_all[e]] += sto_all[e] * v[rxn_all[e]]
// ---------------------------------------------------------------------------
__global__ __launch_bounds__(256)
void dxdt_kernel(const float* __restrict__ sto_all,
                 const int*   __restrict__ rxn_all,
                 const int*   __restrict__ met_all,
                 const float* __restrict__ v,
                 float* __restrict__ dxdt) {
    int i4 = blockIdx.x * blockDim.x + threadIdx.x;   // one thread = 4 edges
    if (i4 >= E_ALL / 4) return;
    float4 sv = reinterpret_cast<const float4*>(sto_all)[i4];
    int4   rv = reinterpret_cast<const int4*>(rxn_all)[i4];
    int4   mv = reinterpret_cast<const int4*>(met_all)[i4];
    red_add_f32(dxdt + mv.x, sv.x * __ldg(v + rv.x));
    red_add_f32(dxdt + mv.y, sv.y * __ldg(v + rv.y));
    red_add_f32(dxdt + mv.z, sv.z * __ldg(v + rv.z));
    red_add_f32(dxdt + mv.w, sv.w * __ldg(v + rv.w));
}

// ---------------------------------------------------------------------------
// Launch.  Inputs (metadata order):
//  0 x_met[100000] f32, 1 sto_sub[2M] f32, 2 sto_all[4M] f32,
//  3 W1m[64], 4 b1m[32], 5 W2m[512], 6 b2m[16],
//  7 W1r[512], 8 b1r[32], 9 W2r[32], 10 b2r[1],
//  11 met_sub[2M] i32, 12 rxn_sub[2M] i32, 13 met_all[4M] i32, 14 rxn_all[4M] i32
// Output: dxdt[100000] then v[50000] (float32)
// ---------------------------------------------------------------------------
extern "C" void kernel_launch(void* const* d_in, const int* in_sizes, int n_in,
                              void* d_out, int out_size) {
    const float* x_met   = (const float*)d_in[0];
    const float* sto_sub = (const float*)d_in[1];
    const float* sto_all = (const float*)d_in[2];
    const float* W1m     = (const float*)d_in[3];
    const float* b1m     = (const float*)d_in[4];
    const float* W2m     = (const float*)d_in[5];
    const float* b2m     = (const float*)d_in[6];
    const float* W1r     = (const float*)d_in[7];
    const float* b1r     = (const float*)d_in[8];
    const float* W2r     = (const float*)d_in[9];
    const float* b2r     = (const float*)d_in[10];
    const int*   met_sub = (const int*)d_in[11];
    const int*   rxn_sub = (const int*)d_in[12];
    const int*   met_all = (const int*)d_in[13];
    const int*   rxn_all = (const int*)d_in[14];

    float* dxdt = (float*)d_out;
    float* v    = (float*)d_out + N_MET;

    // K0: zero scratch + dxdt
    zero_kernel<<<256, 256>>>(dxdt);

    // K1: edge message MLP + scatter into g_hrxn
    int grid1 = (E_SUB + K1_EPB - 1) / K1_EPB;
    edge_msg_kernel<<<grid1, K1_TPB>>>(x_met, sto_sub, W1m, b1m, W2m, b2m,
                                       met_sub, rxn_sub);

    // K2: reaction rate MLP -> v
    rate_kernel<<<(N_RXN + 255) / 256, 256>>>(W1r, b1r, W2r, b2r, v);

    // K3: dxdt scatter
    dxdt_kernel<<<(E_ALL / 4 + 255) / 256, 256>>>(sto_all, rxn_all, met_all, v, dxdt);
}